// round 15
// baseline (speedup 1.0000x reference)
#include <cuda_runtime.h>
#include <cuda_bf16.h>
#include <math.h>
#include <mma.h>

using namespace nvcuda;

#define NN     2048
#define EE     16384
#define BBATCH 32
#define TP2    61
#define DD     128
#define C3N    32

typedef unsigned long long u64b;

__device__ __forceinline__ void fma2(u64b& d, u64b a, u64b b) {
    asm("fma.rn.f32x2 %0, %1, %2, %0;" : "+l"(d) : "l"(a), "l"(b));
}
__device__ __forceinline__ float hsum2(u64b v) {
    float lo, hi;
    asm("mov.b64 {%0,%1}, %2;" : "=f"(lo), "=f"(hi) : "l"(v));
    return lo + hi;
}
__device__ __forceinline__ u64b expand_bf2(unsigned u) {
    unsigned lo = u << 16;
    unsigned hi = u & 0xffff0000u;
    u64b d;
    asm("mov.b64 %0, {%1, %2};" : "=l"(d) : "r"(lo), "r"(hi));
    return d;
}
__device__ __forceinline__ void add2(u64b& d, u64b a) {
    asm("add.rn.f32x2 %0, %0, %1;" : "+l"(d) : "l"(a));
}
__device__ __forceinline__ unsigned bfadd2(unsigned a, unsigned b) {
    unsigned r;
    asm("add.rn.bf16x2 %0, %1, %2;" : "=r"(r) : "r"(a), "r"(b));
    return r;
}
__device__ __forceinline__ void acc_u4(u64b* accp, uint4 b) {
    add2(accp[0], expand_bf2(b.x));
    add2(accp[1], expand_bf2(b.y));
    add2(accp[2], expand_bf2(b.z));
    add2(accp[3], expand_bf2(b.w));
}
__device__ __forceinline__ void acc_pair_u4(u64b* accp, uint4 a, uint4 b) {
    add2(accp[0], expand_bf2(bfadd2(a.x, b.x)));
    add2(accp[1], expand_bf2(bfadd2(a.y, b.y)));
    add2(accp[2], expand_bf2(bfadd2(a.z, b.z)));
    add2(accp[3], expand_bf2(bfadd2(a.w, b.w)));
}
__device__ __forceinline__ unsigned pair_to_bf2(u64b d) {
    float lo, hi; unsigned r;
    asm("mov.b64 {%0,%1}, %2;" : "=f"(lo), "=f"(hi) : "l"(d));
    asm("cvt.rn.bf16x2.f32 %0, %1, %2;" : "=r"(r) : "f"(hi), "f"(lo));
    return r;
}
__device__ __forceinline__ unsigned bf2pack(float lo, float hi) {
    unsigned r;
    asm("cvt.rn.bf16x2.f32 %0, %1, %2;" : "=r"(r) : "f"(hi), "f"(lo));
    return r;
}

// ---------------- scratch ----------------
__device__ __nv_bfloat16 g_h0[NN * TP2 * C3N];
__device__ __nv_bfloat16 g_h1[NN * TP2 * DD];
__device__ float g_dwt[TP2 * DD * 4];
__device__ float g_contrib[NN * 4];
__device__ float g_dinv[NN];
__device__ int   g_cnt[NN];
__device__ int   g_cur[NN];
__device__ int   g_off[NN + 1];
__device__ int   g_col[EE];

// ---------------- graph prep ----------------
// zero counters + transpose dense weights (merged)
__global__ void zero_dwt_kernel(const float* __restrict__ dw) {
    int i = blockIdx.x * blockDim.x + threadIdx.x;
    if (i < NN) g_cnt[i] = 0;
    for (int j = i; j < TP2 * DD; j += 2048) {
        int t = j >> 7, d = j & 127;
        *(float4*)&g_dwt[j * 4] = *(const float4*)&dw[(size_t)(d * TP2 + t) * 4];
    }
}

__global__ void count_kernel(const int* __restrict__ ei) {
    int e = blockIdx.x * blockDim.x + threadIdx.x;
    if (e < EE) atomicAdd(&g_cnt[ei[EE + e]], 1);
}

__global__ void scan_kernel() {
    __shared__ int csum[256];
    const int tid = threadIdx.x;
    const int base = tid * 8;
    int local[8];
    int s = 0;
#pragma unroll
    for (int i = 0; i < 8; i++) { local[i] = s; s += g_cnt[base + i]; }
    csum[tid] = s;
    __syncthreads();
    for (int ofs = 1; ofs < 256; ofs <<= 1) {
        int v = (tid >= ofs) ? csum[tid - ofs] : 0;
        __syncthreads();
        csum[tid] += v;
        __syncthreads();
    }
    int pre = (tid == 0) ? 0 : csum[tid - 1];
#pragma unroll
    for (int i = 0; i < 8; i++) {
        int o = pre + local[i];
        g_off[base + i] = o;
        g_cur[base + i] = o;
        g_dinv[base + i] = rsqrtf((float)(g_cnt[base + i] + 1));
    }
    if (tid == 255) g_off[NN] = pre + s;
}

__global__ void fill_kernel(const int* __restrict__ ei) {
    int e = blockIdx.x * blockDim.x + threadIdx.x;
    if (e < EE) {
        int src = ei[e];
        int dst = ei[EE + e];
        int p = atomicAdd(&g_cur[dst], 1);
        g_col[p] = src;
    }
}

// ---------------- fused CNN + pos-MLP (one block per node, f32x2, 3 CTA/SM) ----------------
#define SXP_O   0
#define H1B_O   1048
#define U1_O    5160
#define H2_O    0
#define U2_O    4048
#define W3K_O   8016
#define W1E_O   13352
#define W1O_O   13544
#define W1X_O   13736
#define W2K_O   13752
#define S1_O    15800
#define B1_O    15808
#define S2_O    15816
#define B2_O    15832
#define S3_O    15848
#define B3_O    15880
#define PE_O    15912
#define HID_O   15944
#define CONV_SMEM_FLOATS 15976
#define CONV_SMEM_BYTES (CONV_SMEM_FLOATS * 4)

__global__ __launch_bounds__(256, 3) void conv_kernel(
    const float* __restrict__ x,   const float* __restrict__ pos,
    const float* __restrict__ c1w, const float* __restrict__ c1b,
    const float* __restrict__ g1,  const float* __restrict__ b1,
    const float* __restrict__ c2w, const float* __restrict__ c2b,
    const float* __restrict__ g2,  const float* __restrict__ b2,
    const float* __restrict__ c3w, const float* __restrict__ c3b,
    const float* __restrict__ g3,  const float* __restrict__ b3,
    const float* __restrict__ pw1, const float* __restrict__ pb1,
    const float* __restrict__ pw2, const float* __restrict__ pb2,
    __nv_bfloat16* __restrict__ out)
{
    extern __shared__ float sm[];
    unsigned* smu = (unsigned*)sm;
    const int n = blockIdx.x;
    const int tid = threadIdx.x;
    const float rs = rsqrtf(1.0f + 1e-5f);
    const float dvn = g_dinv[n];

    for (int i = tid; i < 96; i += 256) {
        int c = i / 12, m = i % 12;
        sm[W1E_O + 2 * i]     = c1w[c * 25 + 2 * m];
        sm[W1E_O + 2 * i + 1] = c1w[c * 25 + 2 * m + 1];
    }
    for (int i = tid; i < 96; i += 256) {
        int c = i / 12, m = i % 12;
        sm[W1O_O + 2 * i]     = c1w[c * 25 + 2 * m + 1];
        sm[W1O_O + 2 * i + 1] = c1w[c * 25 + 2 * m + 2];
    }
    if (tid < 8)  sm[W1X_O + tid] = c1w[tid * 25];
    else if (tid < 16) sm[W1X_O + tid] = c1w[(tid - 8) * 25 + 24];
    for (int i = tid; i < 512; i += 256) {
        int ci = i >> 6, m = (i >> 3) & 7, q = i & 7;
        int base = q * 120 + ci * 15 + 2 * m;
        float4 v;
        v.x = c2w[base];
        v.y = (2 * m + 1 < 15) ? c2w[base + 1] : 0.f;
        v.z = c2w[base + 960];
        v.w = (2 * m + 1 < 15) ? c2w[base + 961] : 0.f;
        *(float4*)&sm[W2K_O + 4 * i] = v;
    }
    if (tid < 8) {
        float s = g1[tid] * rs; sm[S1_O + tid] = s; sm[B1_O + tid] = c1b[tid] * s + b1[tid];
    } else if (tid >= 32 && tid < 48) {
        int c = tid - 32; float s = g2[c] * rs; sm[S2_O + c] = s; sm[B2_O + c] = c2b[c] * s + b2[c];
    } else if (tid >= 64 && tid < 96) {
        int c = tid - 64; float s = g3[c] * rs; sm[S3_O + c] = s; sm[B3_O + c] = c3b[c] * s + b3[c];
    }
    if (tid >= 128 && tid < 160) {
        int c = tid - 128;
        float p0 = pos[n * 3 + 0], p1 = pos[n * 3 + 1], p2 = pos[n * 3 + 2];
        float h = p0 * pw1[c] + p1 * pw1[32 + c] + p2 * pw1[64 + c] + pb1[c];
        sm[HID_O + c] = fmaxf(h, 0.f);
    }
    for (int i = tid; i < 1024; i += 256) sm[SXP_O + 12 + i] = x[(size_t)n * 1024 + i];
    if (tid < 12) { sm[SXP_O + tid] = 0.f; sm[SXP_O + 1036 + tid] = 0.f; }
    __syncthreads();

    if (tid < 32) {
        float s = pb2[tid];
#pragma unroll
        for (int j = 0; j < 32; j++) s += sm[HID_O + j] * pw2[j * 32 + tid];
        sm[PE_O + tid] = s;
    }

    // conv1 (1->8, K=25) + BN + relu, write bf16 h1b
    {
        const int t0 = tid * 4;
        union UU { float4 q[7]; u64b p[14]; float f[28]; } uu;
#pragma unroll
        for (int i = 0; i < 7; i++) uu.q[i] = *(const float4*)&sm[SXP_O + t0 + 4 * i];
        const u64b* w1e = (const u64b*)&sm[W1E_O];
        const u64b* w1o = (const u64b*)&sm[W1O_O];
#pragma unroll
        for (int c = 0; c < 8; c++) {
            u64b a0 = 0, a1 = 0, a2 = 0, a3 = 0;
#pragma unroll
            for (int m = 0; m < 12; m++) {
                u64b we = w1e[c * 12 + m];
                fma2(a0, we, uu.p[m]);
                fma2(a2, we, uu.p[m + 1]);
                u64b wo = w1o[c * 12 + m];
                fma2(a1, wo, uu.p[m + 1]);
                fma2(a3, wo, uu.p[m + 2]);
            }
            float w0 = sm[W1X_O + c], w24 = sm[W1X_O + 8 + c];
            float v0 = hsum2(a0) + w24 * uu.f[24];
            float v1 = hsum2(a1) + w0  * uu.f[1];
            float v2 = hsum2(a2) + w24 * uu.f[26];
            float v3 = hsum2(a3) + w0  * uu.f[3];
            float s = sm[S1_O + c], B = sm[B1_O + c];
            float o0 = fmaxf(v0 * s + B, 0.f);
            float o1 = fmaxf(v1 * s + B, 0.f);
            float o2 = fmaxf(v2 * s + B, 0.f);
            float o3 = fmaxf(v3 * s + B, 0.f);
            uint2 pk;
            pk.x = bf2pack(o0, o1);
            pk.y = bf2pack(o2, o3);
            *(uint2*)&smu[H1B_O + c * 514 + (t0 >> 1)] = pk;
        }
    }
    __syncthreads();

    // pool1: u1 (f32) from bf16 h1b
    for (int c = 0; c < 8; c++) {
        const unsigned* hb = &smu[H1B_O + c * 514];
        for (int j2 = tid; j2 < 510; j2 += 256) {
            unsigned a = hb[j2], b = hb[j2 + 1], d = hb[j2 + 2];
            float a0 = __uint_as_float(a << 16), a1 = __uint_as_float(a & 0xffff0000u);
            float b0 = __uint_as_float(b << 16), b1 = __uint_as_float(b & 0xffff0000u);
            float d0 = __uint_as_float(d << 16);
            float mid = a1 + b0 + b1;
            sm[U1_O + c * 1024 + 2 * j2]     = 0.25f * (a0 + mid);
            sm[U1_O + c * 1024 + 2 * j2 + 1] = 0.25f * (mid + d0);
        }
    }
    __syncthreads();

    // conv2 (8->16, K=15 padded 16) fused pool4 + BN + relu -> h2 (f32)
    {
        const int q = tid & 7, tpq = tid >> 3;
        u64b accL[8], accH[8];
#pragma unroll
        for (int it = 0; it < 8; it++) { accL[it] = 0; accH[it] = 0; }
#pragma unroll
        for (int ci = 0; ci < 8; ci++) {
            union WU { float4 v; u64b p[2]; } wv[8];
#pragma unroll
            for (int m = 0; m < 8; m++)
                wv[m].v = *(const float4*)&sm[W2K_O + 4 * ((ci * 8 + m) * 8 + q)];
#pragma unroll
            for (int it = 0; it < 8; it++) {
                int tp = tpq + 32 * it;
                if (tp < 252) {
                    union UB { float4 v[4]; u64b p[8]; } ub;
                    const float4* up = (const float4*)&sm[U1_O + ci * 1024 + 4 * tp];
#pragma unroll
                    for (int i = 0; i < 4; i++) ub.v[i] = up[i];
#pragma unroll
                    for (int m = 0; m < 8; m++) {
                        fma2(accL[it], wv[m].p[0], ub.p[m]);
                        fma2(accH[it], wv[m].p[1], ub.p[m]);
                    }
                }
            }
        }
        float sL = sm[S2_O + q], BL = sm[B2_O + q];
        float sH = sm[S2_O + q + 8], BH = sm[B2_O + q + 8];
#pragma unroll
        for (int it = 0; it < 8; it++) {
            int tp = tpq + 32 * it;
            if (tp < 252) {
                sm[H2_O + q * 253 + tp]       = fmaxf(hsum2(accL[it]) * sL + BL, 0.f);
                sm[H2_O + (q + 8) * 253 + tp] = fmaxf(hsum2(accH[it]) * sH + BH, 0.f);
            }
        }
    }
    __syncthreads();

    // pool2 (u2) + late load of conv3 weights into dead u1 space
    for (int i = tid; i < 1024; i += 256) {
        int ci = i >> 6, m = (i >> 4) & 3, q = i & 15;
        int base = q * 112 + ci * 7 + 2 * m;
        float4 v;
        v.x = c3w[base];
        v.y = (2 * m + 1 < 7) ? c3w[base + 1] : 0.f;
        v.z = c3w[base + 1792];
        v.w = (2 * m + 1 < 7) ? c3w[base + 1793] : 0.f;
        *(float4*)&sm[W3K_O + 4 * i] = v;
    }
    for (int j = tid; j < 16 * 248; j += 256) {
        int c = j / 248, jj = j % 248;
        const float* hr = &sm[H2_O + c * 253 + jj];
        sm[U2_O + c * 248 + jj] = 0.25f * (hr[0] + hr[1] + hr[2] + hr[3]);
    }
    __syncthreads();

    // conv3 (16->32, K=7 padded 8) fused pool4 + pe, write bf16 pre-scaled by dinv[n]
    {
        const int q = tid & 15, tpq = tid >> 4;
        u64b accL[4], accH[4];
#pragma unroll
        for (int it = 0; it < 4; it++) { accL[it] = 0; accH[it] = 0; }
#pragma unroll
        for (int ci = 0; ci < 16; ci++) {
            union WU { float4 v; u64b p[2]; } wv[4];
#pragma unroll
            for (int m = 0; m < 4; m++)
                wv[m].v = *(const float4*)&sm[W3K_O + 4 * ((ci * 4 + m) * 16 + q)];
#pragma unroll
            for (int it = 0; it < 4; it++) {
                int tp = tpq + 16 * it;
                if (tp < 61) {
                    union UB { float4 v[2]; u64b p[4]; } ub;
                    const float4* up = (const float4*)&sm[U2_O + ci * 248 + 4 * tp];
                    ub.v[0] = up[0]; ub.v[1] = up[1];
#pragma unroll
                    for (int m = 0; m < 4; m++) {
                        fma2(accL[it], wv[m].p[0], ub.p[m]);
                        fma2(accH[it], wv[m].p[1], ub.p[m]);
                    }
                }
            }
        }
        float sL = sm[S3_O + q], BL = sm[B3_O + q], peL = sm[PE_O + q];
        float sH = sm[S3_O + q + 16], BH = sm[B3_O + q + 16], peH = sm[PE_O + q + 16];
#pragma unroll
        for (int it = 0; it < 4; it++) {
            int tp = tpq + 16 * it;
            if (tp < 61) {
                size_t base = ((size_t)n * 61 + tp) * 32;
                out[base + q]      = __float2bfloat16((fmaxf(hsum2(accL[it]) * sL + BL, 0.f) + peL) * dvn);
                out[base + q + 16] = __float2bfloat16((fmaxf(hsum2(accH[it]) * sH + BH, 0.f) + peH) * dvn);
            }
        }
    }
}

// ---------------- fused GCN layer (2 nodes/block, M=128 tile) ----------------
template <int K, bool DO_CONTRIB>
__global__ __launch_bounds__(256, 2) void gcn_fused_kernel(
    const __nv_bfloat16* __restrict__ h, const float* __restrict__ W,
    const float* __restrict__ bias, __nv_bfloat16* __restrict__ out)
{
    constexpr int LDA = K + 8;
    constexpr int LDW = 136;
    constexpr int LDC = 132;
    constexpr int V8 = TP2 * K / 8;
    constexpr int VPT = (V8 + 255) / 256;
    extern __shared__ char sgc[];
    __nv_bfloat16* ws = (__nv_bfloat16*)sgc;
    __nv_bfloat16* as = ws + K * LDW;
    float* cs = (float*)sgc;
    __shared__ float bs[128];
    __shared__ float red[8][4];

    const int tid = threadIdx.x;
    const int bid = blockIdx.x;

    if (tid < 128) bs[tid] = bias[tid];
    for (int i = tid; i < K * 32; i += 256) {
        int k = i >> 5, c4 = i & 31;
        float4 v = *(const float4*)&W[k * 128 + c4 * 4];
        __nv_bfloat16* p = &ws[k * LDW + c4 * 4];
        p[0] = __float2bfloat16(v.x); p[1] = __float2bfloat16(v.y);
        p[2] = __float2bfloat16(v.z); p[3] = __float2bfloat16(v.w);
    }
    for (int i = tid; i < 6 * (K / 8); i += 256) {
        int r = 122 + i / (K / 8), c8 = i % (K / 8);
        *(uint4*)&as[r * LDA + c8 * 8] = make_uint4(0, 0, 0, 0);
    }

#pragma unroll 1
    for (int nh = 0; nh < 2; nh++) {
        const int n = 2 * bid + nh;
        const uint4* hn = (const uint4*)(h + (size_t)n * (TP2 * K));
        u64b accp[VPT][4];
#pragma unroll
        for (int v = 0; v < VPT; v++) {
            int i = tid + v * 256;
            if (i < V8) {
                uint4 b = hn[i];
                accp[v][0] = expand_bf2(b.x);
                accp[v][1] = expand_bf2(b.y);
                accp[v][2] = expand_bf2(b.z);
                accp[v][3] = expand_bf2(b.w);
            }
        }
        const int jb = g_off[n], je = g_off[n + 1];
        int e = jb;
        if (VPT == 1) {
            for (; e + 4 <= je; e += 4) {
                const uint4* p0 = (const uint4*)(h + (size_t)g_col[e]     * (TP2 * K));
                const uint4* p1 = (const uint4*)(h + (size_t)g_col[e + 1] * (TP2 * K));
                const uint4* p2 = (const uint4*)(h + (size_t)g_col[e + 2] * (TP2 * K));
                const uint4* p3 = (const uint4*)(h + (size_t)g_col[e + 3] * (TP2 * K));
                if (tid < V8) {
                    uint4 b0 = p0[tid], b1 = p1[tid], b2 = p2[tid], b3 = p3[tid];
                    acc_pair_u4(accp[0], b0, b1);
                    acc_pair_u4(accp[0], b2, b3);
                }
            }
        } else {
            // 3-edge unroll: 12 uint4 in flight per thread
            for (; e + 3 <= je; e += 3) {
                const uint4* p0 = (const uint4*)(h + (size_t)g_col[e]     * (TP2 * K));
                const uint4* p1 = (const uint4*)(h + (size_t)g_col[e + 1] * (TP2 * K));
                const uint4* p2 = (const uint4*)(h + (size_t)g_col[e + 2] * (TP2 * K));
                uint4 b0[VPT], b1[VPT], b2[VPT];
#pragma unroll
                for (int v = 0; v < VPT; v++) {
                    int i = tid + v * 256;
                    if (i < V8) { b0[v] = p0[i]; b1[v] = p1[i]; b2[v] = p2[i]; }
                }
#pragma unroll
                for (int v = 0; v < VPT; v++) {
                    int i = tid + v * 256;
                    if (i < V8) { acc_pair_u4(accp[v], b0[v], b1[v]); acc_u4(accp[v], b2[v]); }
                }
            }
        }
        for (; e + 2 <= je; e += 2) {
            const uint4* p0 = (const uint4*)(h + (size_t)g_col[e]     * (TP2 * K));
            const uint4* p1 = (const uint4*)(h + (size_t)g_col[e + 1] * (TP2 * K));
            uint4 b0[VPT], b1[VPT];
#pragma unroll
            for (int v = 0; v < VPT; v++) {
                int i = tid + v * 256;
                if (i < V8) { b0[v] = p0[i]; b1[v] = p1[i]; }
            }
#pragma unroll
            for (int v = 0; v < VPT; v++) {
                int i = tid + v * 256;
                if (i < V8) acc_pair_u4(accp[v], b0[v], b1[v]);
            }
        }
        if (e < je) {
            const uint4* p0 = (const uint4*)(h + (size_t)g_col[e] * (TP2 * K));
#pragma unroll
            for (int v = 0; v < VPT; v++) {
                int i = tid + v * 256;
                if (i < V8) acc_u4(accp[v], p0[i]);
            }
        }
#pragma unroll
        for (int v = 0; v < VPT; v++) {
            int i = tid + v * 256;
            if (i < V8) {
                int r = nh * TP2 + i / (K / 8), c8 = i % (K / 8);
                uint4 o;
                o.x = pair_to_bf2(accp[v][0]);
                o.y = pair_to_bf2(accp[v][1]);
                o.z = pair_to_bf2(accp[v][2]);
                o.w = pair_to_bf2(accp[v][3]);
                *(uint4*)&as[r * LDA + c8 * 8] = o;
            }
        }
    }
    __syncthreads();

    const int wid = tid >> 5;
    const int wr = wid & 3;
    const int wc = wid >> 2;
    wmma::fragment<wmma::accumulator, 16, 16, 16, float> cf[2][4];
#pragma unroll
    for (int i = 0; i < 2; i++)
#pragma unroll
        for (int j = 0; j < 4; j++) wmma::fill_fragment(cf[i][j], 0.f);

#pragma unroll
    for (int k0 = 0; k0 < K; k0 += 16) {
        wmma::fragment<wmma::matrix_a, 16, 16, 16, __nv_bfloat16, wmma::row_major> af[2];
#pragma unroll
        for (int i = 0; i < 2; i++)
            wmma::load_matrix_sync(af[i], as + (wr * 32 + i * 16) * LDA + k0, LDA);
        wmma::fragment<wmma::matrix_b, 16, 16, 16, __nv_bfloat16, wmma::row_major> bf[4];
#pragma unroll
        for (int j = 0; j < 4; j++)
            wmma::load_matrix_sync(bf[j], ws + k0 * LDW + wc * 64 + j * 16, LDW);
#pragma unroll
        for (int i = 0; i < 2; i++)
#pragma unroll
            for (int j = 0; j < 4; j++)
                wmma::mma_sync(cf[i][j], af[i], bf[j], cf[i][j]);
    }
    __syncthreads();
#pragma unroll
    for (int i = 0; i < 2; i++)
#pragma unroll
        for (int j = 0; j < 4; j++)
            wmma::store_matrix_sync(cs + (wr * 32 + i * 16) * LDC + wc * 64 + j * 16,
                                    cf[i][j], LDC, wmma::mem_row_major);
    __syncthreads();

    if (!DO_CONTRIB) {
        for (int idx = tid; idx < 128 * 64; idx += 256) {
            int r = idx >> 6, c2 = idx & 63;
            if (r < 122) {
                int nh = (r >= TP2) ? 1 : 0;
                int n = 2 * bid + nh;
                int t = r - TP2 * nh;
                float dv = g_dinv[n];
                float v0 = fmaxf(cs[r * LDC + 2 * c2]     * dv + bs[2 * c2], 0.f) * dv;
                float v1 = fmaxf(cs[r * LDC + 2 * c2 + 1] * dv + bs[2 * c2 + 1], 0.f) * dv;
                ((__nv_bfloat162*)out)[(size_t)(n * TP2 + t) * 64 + c2] =
                    __floats2bfloat162_rn(v0, v1);
            }
        }
    } else {
        const int half = tid >> 7, d = tid & 127;
        const int n = 2 * bid + half;
        const float dv = g_dinv[n];
        const float bsv = bs[d];
        float a0 = 0.f, a1 = 0.f, a2 = 0.f, a3 = 0.f;
#pragma unroll 4
        for (int t = 0; t < TP2; t++) {
            float v = fmaxf(cs[(half * TP2 + t) * LDC + d] * dv + bsv, 0.f);
            const float4 w = *(const float4*)&g_dwt[(size_t)(t * DD + d) * 4];
            a0 += v * w.x; a1 += v * w.y; a2 += v * w.z; a3 += v * w.w;
        }
#pragma unroll
        for (int o = 16; o > 0; o >>= 1) {
            a0 += __shfl_down_sync(0xffffffff, a0, o);
            a1 += __shfl_down_sync(0xffffffff, a1, o);
            a2 += __shfl_down_sync(0xffffffff, a2, o);
            a3 += __shfl_down_sync(0xffffffff, a3, o);
        }
        const int wid2 = tid >> 5;
        if ((tid & 31) == 0) {
            red[wid2][0] = a0; red[wid2][1] = a1; red[wid2][2] = a2; red[wid2][3] = a3;
        }
        __syncthreads();
        if (tid < 8) {
            int hh = tid >> 2, j = tid & 3;
            float s = red[hh * 4 + 0][j] + red[hh * 4 + 1][j]
                    + red[hh * 4 + 2][j] + red[hh * 4 + 3][j];
            g_contrib[(2 * bid + hh) * 4 + j] = s;
        }
    }
}

// ---------------- batch pooling + bias + log_softmax ----------------
__global__ __launch_bounds__(256) void final_kernel(
    const int* __restrict__ batch, const float* __restrict__ db,
    float* __restrict__ out)
{
    const int b = blockIdx.x, tid = threadIdx.x;
    float a0 = 0.f, a1 = 0.f, a2 = 0.f, a3 = 0.f;
    int c = 0;
    for (int n = tid; n < NN; n += 256) {
        if (batch[n] == b) {
            const float4 v = *(const float4*)&g_contrib[n * 4];
            a0 += v.x; a1 += v.y; a2 += v.z; a3 += v.w;
            c++;
        }
    }
    __shared__ float r0[256], r1[256], r2[256], r3[256];
    __shared__ int rc[256];
    r0[tid] = a0; r1[tid] = a1; r2[tid] = a2; r3[tid] = a3; rc[tid] = c;
    __syncthreads();
    for (int s = 128; s > 0; s >>= 1) {
        if (tid < s) {
            r0[tid] += r0[tid + s]; r1[tid] += r1[tid + s];
            r2[tid] += r2[tid + s]; r3[tid] += r3[tid + s];
            rc[tid] += rc[tid + s];
        }
        __syncthreads();
    }
    if (tid == 0) {
        float cc = fmaxf((float)rc[0], 1.f);
        float l0 = r0[0] / cc + db[0];
        float l1 = r1[0] / cc + db[1];
        float l2 = r2[0] / cc + db[2];
        float l3 = r3[0] / cc + db[3];
        float m = fmaxf(fmaxf(l0, l1), fmaxf(l2, l3));
        float sum = expf(l0 - m) + expf(l1 - m) + expf(l2 - m) + expf(l3 - m);
        float ls = logf(sum);
        out[b * 4 + 0] = l0 - m - ls;
        out[b * 4 + 1] = l1 - m - ls;
        out[b * 4 + 2] = l2 - m - ls;
        out[b * 4 + 3] = l3 - m - ls;
    }
}

// ---------------- launch ----------------
extern "C" void kernel_launch(void* const* d_in, const int* in_sizes, int n_in,
                              void* d_out, int out_size)
{
    const float* x   = (const float*)d_in[0];
    const float* pos = (const float*)d_in[1];
    const float* c1w = (const float*)d_in[2];
    const float* c1b = (const float*)d_in[3];
    const float* bg1 = (const float*)d_in[4];
    const float* bb1 = (const float*)d_in[5];
    const float* c2w = (const float*)d_in[6];
    const float* c2b = (const float*)d_in[7];
    const float* bg2 = (const float*)d_in[8];
    const float* bb2 = (const float*)d_in[9];
    const float* c3w = (const float*)d_in[10];
    const float* c3b = (const float*)d_in[11];
    const float* bg3 = (const float*)d_in[12];
    const float* bb3 = (const float*)d_in[13];
    const float* pw1 = (const float*)d_in[14];
    const float* pb1 = (const float*)d_in[15];
    const float* pw2 = (const float*)d_in[16];
    const float* pb2 = (const float*)d_in[17];
    const float* gw1 = (const float*)d_in[18];
    const float* gb1 = (const float*)d_in[19];
    const float* gw2 = (const float*)d_in[20];
    const float* gb2 = (const float*)d_in[21];
    const float* dw  = (const float*)d_in[22];
    const float* db  = (const float*)d_in[23];
    const int*   ei  = (const int*)d_in[24];
    const int*   bat = (const int*)d_in[25];
    float* out = (float*)d_out;

    const int g1_smem = 128 * 132 * 4;                    // 67584
    const int g2_smem = (128 * 136 + 128 * 136) * 2;      // 69632

    cudaFuncSetAttribute(conv_kernel, cudaFuncAttributeMaxDynamicSharedMemorySize, CONV_SMEM_BYTES);
    cudaFuncSetAttribute(gcn_fused_kernel<32, false>,  cudaFuncAttributeMaxDynamicSharedMemorySize, g1_smem);
    cudaFuncSetAttribute(gcn_fused_kernel<128, true>,  cudaFuncAttributeMaxDynamicSharedMemorySize, g2_smem);

    __nv_bfloat16 *h0, *h1;
    cudaGetSymbolAddress((void**)&h0, g_h0);
    cudaGetSymbolAddress((void**)&h1, g_h1);

    // conv is 4th launch (profiled); it only needs scan's dinv. fill runs after.
    zero_dwt_kernel<<<8, 256>>>(dw);
    count_kernel<<<64, 256>>>(ei);
    scan_kernel<<<1, 256>>>();

    conv_kernel<<<NN, 256, CONV_SMEM_BYTES>>>(
        x, pos, c1w, c1b, bg1, bb1, c2w, c2b, bg2, bb2,
        c3w, c3b, bg3, bb3, pw1, pb1, pw2, pb2, h0);

    fill_kernel<<<64, 256>>>(ei);

    gcn_fused_kernel<32, false><<<NN / 2, 256, g1_smem>>>(h0, gw1, gb1, h1);
    gcn_fused_kernel<128, true><<<NN / 2, 256, g2_smem>>>(h1, gw2, gb2, nullptr);

    final_kernel<<<BBATCH, 256>>>(bat, db, out);
}

// round 16
// speedup vs baseline: 1.0144x; 1.0144x over previous
#include <cuda_runtime.h>
#include <cuda_bf16.h>
#include <math.h>
#include <mma.h>

using namespace nvcuda;

#define NN     2048
#define EE     16384
#define BBATCH 32
#define TP2    61
#define DD     128
#define C3N    32

typedef unsigned long long u64b;

__device__ __forceinline__ void fma2(u64b& d, u64b a, u64b b) {
    asm("fma.rn.f32x2 %0, %1, %2, %0;" : "+l"(d) : "l"(a), "l"(b));
}
__device__ __forceinline__ float hsum2(u64b v) {
    float lo, hi;
    asm("mov.b64 {%0,%1}, %2;" : "=f"(lo), "=f"(hi) : "l"(v));
    return lo + hi;
}
__device__ __forceinline__ u64b expand_bf2(unsigned u) {
    unsigned lo = u << 16;
    unsigned hi = u & 0xffff0000u;
    u64b d;
    asm("mov.b64 %0, {%1, %2};" : "=l"(d) : "r"(lo), "r"(hi));
    return d;
}
__device__ __forceinline__ void add2(u64b& d, u64b a) {
    asm("add.rn.f32x2 %0, %0, %1;" : "+l"(d) : "l"(a));
}
__device__ __forceinline__ unsigned bfadd2(unsigned a, unsigned b) {
    unsigned r;
    asm("add.rn.bf16x2 %0, %1, %2;" : "=r"(r) : "r"(a), "r"(b));
    return r;
}
__device__ __forceinline__ void acc_u4(u64b* accp, uint4 b) {
    add2(accp[0], expand_bf2(b.x));
    add2(accp[1], expand_bf2(b.y));
    add2(accp[2], expand_bf2(b.z));
    add2(accp[3], expand_bf2(b.w));
}
__device__ __forceinline__ void acc_pair_u4(u64b* accp, uint4 a, uint4 b) {
    add2(accp[0], expand_bf2(bfadd2(a.x, b.x)));
    add2(accp[1], expand_bf2(bfadd2(a.y, b.y)));
    add2(accp[2], expand_bf2(bfadd2(a.z, b.z)));
    add2(accp[3], expand_bf2(bfadd2(a.w, b.w)));
}
__device__ __forceinline__ unsigned pair_to_bf2(u64b d) {
    float lo, hi; unsigned r;
    asm("mov.b64 {%0,%1}, %2;" : "=f"(lo), "=f"(hi) : "l"(d));
    asm("cvt.rn.bf16x2.f32 %0, %1, %2;" : "=r"(r) : "f"(hi), "f"(lo));
    return r;
}
__device__ __forceinline__ unsigned bf2pack(float lo, float hi) {
    unsigned r;
    asm("cvt.rn.bf16x2.f32 %0, %1, %2;" : "=r"(r) : "f"(hi), "f"(lo));
    return r;
}

// ---------------- scratch ----------------
__device__ __nv_bfloat16 g_h0[NN * TP2 * C3N];
__device__ __nv_bfloat16 g_h1[NN * TP2 * DD];
__device__ float g_dwt[TP2 * DD * 4];
__device__ float g_contrib[NN * 4];
__device__ float g_dinv[NN];
__device__ int   g_cnt[NN];
__device__ int   g_cur[NN];
__device__ int   g_off[NN + 1];
__device__ int   g_col[EE];

// ---------------- graph prep ----------------
__global__ void zero_dwt_kernel(const float* __restrict__ dw) {
    int i = blockIdx.x * blockDim.x + threadIdx.x;
    if (i < NN) g_cnt[i] = 0;
    for (int j = i; j < TP2 * DD; j += 2048) {
        int t = j >> 7, d = j & 127;
        *(float4*)&g_dwt[j * 4] = *(const float4*)&dw[(size_t)(d * TP2 + t) * 4];
    }
}

__global__ void count_kernel(const int* __restrict__ ei) {
    int e = blockIdx.x * blockDim.x + threadIdx.x;
    if (e < EE) atomicAdd(&g_cnt[ei[EE + e]], 1);
}

__global__ void scan_kernel() {
    __shared__ int csum[256];
    const int tid = threadIdx.x;
    const int base = tid * 8;
    int local[8];
    int s = 0;
#pragma unroll
    for (int i = 0; i < 8; i++) { local[i] = s; s += g_cnt[base + i]; }
    csum[tid] = s;
    __syncthreads();
    for (int ofs = 1; ofs < 256; ofs <<= 1) {
        int v = (tid >= ofs) ? csum[tid - ofs] : 0;
        __syncthreads();
        csum[tid] += v;
        __syncthreads();
    }
    int pre = (tid == 0) ? 0 : csum[tid - 1];
#pragma unroll
    for (int i = 0; i < 8; i++) {
        int o = pre + local[i];
        g_off[base + i] = o;
        g_cur[base + i] = o;
        g_dinv[base + i] = rsqrtf((float)(g_cnt[base + i] + 1));
    }
    if (tid == 255) g_off[NN] = pre + s;
}

__global__ void fill_kernel(const int* __restrict__ ei) {
    int e = blockIdx.x * blockDim.x + threadIdx.x;
    if (e < EE) {
        int src = ei[e];
        int dst = ei[EE + e];
        int p = atomicAdd(&g_cur[dst], 1);
        g_col[p] = src;
    }
}

// ---------------- fused CNN + pos-MLP: conv1 f32x2, conv2 WMMA bf16, conv3 f32x2 ----------------
// smem float-slot layout:
//  region X [0,6144): phase1 sxp@0(1048) h1b@1048(4112) | phase2 A@0(1024) h2raw@1024(5120, 256x20)
//  region Y [6144,14408): u1 f32 stride 1028 x8 +40 guard | phase3 u2@6144(3968) w3k@10112(4096)
//  persistent [14408,16008): w1e/w1o/w1x, Btile bf16 (8x16x16), s/B/pe/hid
#define SXP_O   0
#define H1B_O   1048
#define A_O     0
#define H2R_O   1024
#define U1_O    6144
#define U2_O    6144
#define W3K_O   10112
#define W1E_O   14408
#define W1O_O   14600
#define W1X_O   14792
#define BT_O    14808
#define S1_O    15832
#define B1_O    15840
#define S2_O    15848
#define B2_O    15864
#define S3_O    15880
#define B3_O    15912
#define PE_O    15944
#define HID_O   15976
#define CONV_SMEM_FLOATS 16008
#define CONV_SMEM_BYTES (CONV_SMEM_FLOATS * 4)

__global__ __launch_bounds__(256, 3) void conv_kernel(
    const float* __restrict__ x,   const float* __restrict__ pos,
    const float* __restrict__ c1w, const float* __restrict__ c1b,
    const float* __restrict__ g1,  const float* __restrict__ b1,
    const float* __restrict__ c2w, const float* __restrict__ c2b,
    const float* __restrict__ g2,  const float* __restrict__ b2,
    const float* __restrict__ c3w, const float* __restrict__ c3b,
    const float* __restrict__ g3,  const float* __restrict__ b3,
    const float* __restrict__ pw1, const float* __restrict__ pb1,
    const float* __restrict__ pw2, const float* __restrict__ pb2,
    __nv_bfloat16* __restrict__ out)
{
    extern __shared__ float sm[];
    unsigned* smu = (unsigned*)sm;
    const int n = blockIdx.x;
    const int tid = threadIdx.x;
    const float rs = rsqrtf(1.0f + 1e-5f);
    const float dvn = g_dinv[n];

    // conv1 weights (paired)
    for (int i = tid; i < 96; i += 256) {
        int c = i / 12, m = i % 12;
        sm[W1E_O + 2 * i]     = c1w[c * 25 + 2 * m];
        sm[W1E_O + 2 * i + 1] = c1w[c * 25 + 2 * m + 1];
    }
    for (int i = tid; i < 96; i += 256) {
        int c = i / 12, m = i % 12;
        sm[W1O_O + 2 * i]     = c1w[c * 25 + 2 * m + 1];
        sm[W1O_O + 2 * i + 1] = c1w[c * 25 + 2 * m + 2];
    }
    if (tid < 8)  sm[W1X_O + tid] = c1w[tid * 25];
    else if (tid < 16) sm[W1X_O + tid] = c1w[(tid - 8) * 25 + 24];
    // conv2 B tile: Bt[ci][k][c] bf16, k=15 row zero
    {
        __nv_bfloat16* Bt = (__nv_bfloat16*)&sm[BT_O];
        for (int i = tid; i < 2048; i += 256) {
            int ci = i >> 8, k = (i >> 4) & 15, c = i & 15;
            float v = (k < 15) ? c2w[c * 120 + ci * 15 + k] : 0.f;
            Bt[i] = __float2bfloat16(v);
        }
    }
    if (tid < 8) {
        float s = g1[tid] * rs; sm[S1_O + tid] = s; sm[B1_O + tid] = c1b[tid] * s + b1[tid];
    } else if (tid >= 32 && tid < 48) {
        int c = tid - 32; float s = g2[c] * rs; sm[S2_O + c] = s; sm[B2_O + c] = c2b[c] * s + b2[c];
    } else if (tid >= 64 && tid < 96) {
        int c = tid - 64; float s = g3[c] * rs; sm[S3_O + c] = s; sm[B3_O + c] = c3b[c] * s + b3[c];
    }
    if (tid >= 128 && tid < 160) {
        int c = tid - 128;
        float p0 = pos[n * 3 + 0], p1 = pos[n * 3 + 1], p2 = pos[n * 3 + 2];
        float h = p0 * pw1[c] + p1 * pw1[32 + c] + p2 * pw1[64 + c] + pb1[c];
        sm[HID_O + c] = fmaxf(h, 0.f);
    }
    for (int i = tid; i < 1024; i += 256) sm[SXP_O + 12 + i] = x[(size_t)n * 1024 + i];
    if (tid < 12) { sm[SXP_O + tid] = 0.f; sm[SXP_O + 1036 + tid] = 0.f; }
    __syncthreads();

    if (tid < 32) {                       // pos-MLP layer 2
        float s = pb2[tid];
#pragma unroll
        for (int j = 0; j < 32; j++) s += sm[HID_O + j] * pw2[j * 32 + tid];
        sm[PE_O + tid] = s;
    }

    // conv1 (1->8, K=25) + BN + relu, write bf16 h1b
    {
        const int t0 = tid * 4;
        union UU { float4 q[7]; u64b p[14]; float f[28]; } uu;
#pragma unroll
        for (int i = 0; i < 7; i++) uu.q[i] = *(const float4*)&sm[SXP_O + t0 + 4 * i];
        const u64b* w1e = (const u64b*)&sm[W1E_O];
        const u64b* w1o = (const u64b*)&sm[W1O_O];
#pragma unroll
        for (int c = 0; c < 8; c++) {
            u64b a0 = 0, a1 = 0, a2 = 0, a3 = 0;
#pragma unroll
            for (int m = 0; m < 12; m++) {
                u64b we = w1e[c * 12 + m];
                fma2(a0, we, uu.p[m]);
                fma2(a2, we, uu.p[m + 1]);
                u64b wo = w1o[c * 12 + m];
                fma2(a1, wo, uu.p[m + 1]);
                fma2(a3, wo, uu.p[m + 2]);
            }
            float w0 = sm[W1X_O + c], w24 = sm[W1X_O + 8 + c];
            float v0 = hsum2(a0) + w24 * uu.f[24];
            float v1 = hsum2(a1) + w0  * uu.f[1];
            float v2 = hsum2(a2) + w24 * uu.f[26];
            float v3 = hsum2(a3) + w0  * uu.f[3];
            float s = sm[S1_O + c], B = sm[B1_O + c];
            float o0 = fmaxf(v0 * s + B, 0.f);
            float o1 = fmaxf(v1 * s + B, 0.f);
            float o2 = fmaxf(v2 * s + B, 0.f);
            float o3 = fmaxf(v3 * s + B, 0.f);
            uint2 pk;
            pk.x = bf2pack(o0, o1);
            pk.y = bf2pack(o2, o3);
            *(uint2*)&smu[H1B_O + c * 514 + (t0 >> 1)] = pk;
        }
    }
    __syncthreads();

    // pool1: u1 f32 (stride 1028) from bf16 h1b; zero tails + guard
    for (int c = 0; c < 8; c++) {
        const unsigned* hb = &smu[H1B_O + c * 514];
        for (int j2 = tid; j2 < 510; j2 += 256) {
            unsigned a = hb[j2], b = hb[j2 + 1], d = hb[j2 + 2];
            float a0 = __uint_as_float(a << 16), a1 = __uint_as_float(a & 0xffff0000u);
            float b0 = __uint_as_float(b << 16), b1 = __uint_as_float(b & 0xffff0000u);
            float d0 = __uint_as_float(d << 16);
            float mid = a1 + b0 + b1;
            sm[U1_O + c * 1028 + 2 * j2]     = 0.25f * (a0 + mid);
            sm[U1_O + c * 1028 + 2 * j2 + 1] = 0.25f * (mid + d0);
        }
    }
    if (tid < 104) {
        int z = (tid < 64) ? ((tid >> 3) * 1028 + 1020 + (tid & 7)) : (8224 + tid - 64);
        sm[U1_O + z] = 0.f;
    }
    __syncthreads();

    // ---- conv2 via WMMA: 2 chunks of 128 rows, 8 ci steps, fp32 accum -> h2raw ----
    {
        __nv_bfloat16* As = (__nv_bfloat16*)&sm[A_O];
        __nv_bfloat16* Bt = (__nv_bfloat16*)&sm[BT_O];
        float* h2r = &sm[H2R_O];
        const int wid = tid >> 5;
        const int r = tid >> 1, half = tid & 1;
#pragma unroll 1
        for (int chunk = 0; chunk < 2; chunk++) {
            wmma::fragment<wmma::accumulator, 16, 16, 16, float> cf;
            wmma::fill_fragment(cf, 0.f);
#pragma unroll 1
            for (int ci = 0; ci < 8; ci++) {
                const float* up = &sm[U1_O + ci * 1028 + 4 * (chunk * 128 + r) + 8 * half];
                float4 v0 = *(const float4*)up;
                float4 v1 = *(const float4*)(up + 4);
                uint4 o;
                o.x = bf2pack(v0.x, v0.y);
                o.y = bf2pack(v0.z, v0.w);
                o.z = bf2pack(v1.x, v1.y);
                o.w = bf2pack(v1.z, v1.w);
                __syncthreads();   // prior A-fragment loads complete
                *(uint4*)&As[r * 16 + 8 * half] = o;
                __syncthreads();   // A visible
                wmma::fragment<wmma::matrix_a, 16, 16, 16, __nv_bfloat16, wmma::row_major> af;
                wmma::load_matrix_sync(af, As + wid * 256, 16);
                wmma::fragment<wmma::matrix_b, 16, 16, 16, __nv_bfloat16, wmma::row_major> bfr;
                wmma::load_matrix_sync(bfr, Bt + ci * 256, 16);
                wmma::mma_sync(cf, af, bfr, cf);
            }
            wmma::store_matrix_sync(h2r + (chunk * 128 + wid * 16) * 20, cf, 20,
                                    wmma::mem_row_major);
        }
        __syncthreads();
    }

    // ---- pool2: u2[c][j] = mean of relu(bn(h2raw)), + load conv3 weights into dead u1 ----
    for (int c = 0; c < 16; c++) {
        if (tid < 248) {
            float sc = sm[S2_O + c], bb = sm[B2_O + c];
            const float* hr = &sm[H2R_O];
            float s = 0.f;
#pragma unroll
            for (int d = 0; d < 4; d++)
                s += fmaxf(hr[(tid + d) * 20 + c] * sc + bb, 0.f);
            sm[U2_O + c * 248 + tid] = 0.25f * s;
        }
    }
    for (int i = tid; i < 1024; i += 256) {
        int ci = i >> 6, m = (i >> 4) & 3, q = i & 15;
        int base = q * 112 + ci * 7 + 2 * m;
        float4 v;
        v.x = c3w[base];
        v.y = (2 * m + 1 < 7) ? c3w[base + 1] : 0.f;
        v.z = c3w[base + 1792];
        v.w = (2 * m + 1 < 7) ? c3w[base + 1793] : 0.f;
        *(float4*)&sm[W3K_O + 4 * i] = v;
    }
    __syncthreads();

    // conv3 (16->32, K=7 padded 8) fused pool4 + pe, write bf16 pre-scaled by dinv[n]
    {
        const int q = tid & 15, tpq = tid >> 4;
        u64b accL[4], accH[4];
#pragma unroll
        for (int it = 0; it < 4; it++) { accL[it] = 0; accH[it] = 0; }
#pragma unroll
        for (int ci = 0; ci < 16; ci++) {
            union WU { float4 v; u64b p[2]; } wv[4];
#pragma unroll
            for (int m = 0; m < 4; m++)
                wv[m].v = *(const float4*)&sm[W3K_O + 4 * ((ci * 4 + m) * 16 + q)];
#pragma unroll
            for (int it = 0; it < 4; it++) {
                int tp = tpq + 16 * it;
                if (tp < 61) {
                    union UB { float4 v[2]; u64b p[4]; } ub;
                    const float4* up = (const float4*)&sm[U2_O + ci * 248 + 4 * tp];
                    ub.v[0] = up[0]; ub.v[1] = up[1];
#pragma unroll
                    for (int m = 0; m < 4; m++) {
                        fma2(accL[it], wv[m].p[0], ub.p[m]);
                        fma2(accH[it], wv[m].p[1], ub.p[m]);
                    }
                }
            }
        }
        float sL = sm[S3_O + q], BL = sm[B3_O + q], peL = sm[PE_O + q];
        float sH = sm[S3_O + q + 16], BH = sm[B3_O + q + 16], peH = sm[PE_O + q + 16];
#pragma unroll
        for (int it = 0; it < 4; it++) {
            int tp = tpq + 16 * it;
            if (tp < 61) {
                size_t base = ((size_t)n * 61 + tp) * 32;
                out[base + q]      = __float2bfloat16((fmaxf(hsum2(accL[it]) * sL + BL, 0.f) + peL) * dvn);
                out[base + q + 16] = __float2bfloat16((fmaxf(hsum2(accH[it]) * sH + BH, 0.f) + peH) * dvn);
            }
        }
    }
}

// ---------------- fused GCN layer (2 nodes/block, M=128 tile) ----------------
template <int K, bool DO_CONTRIB>
__global__ __launch_bounds__(256, 2) void gcn_fused_kernel(
    const __nv_bfloat16* __restrict__ h, const float* __restrict__ W,
    const float* __restrict__ bias, __nv_bfloat16* __restrict__ out)
{
    constexpr int LDA = K + 8;
    constexpr int LDW = 136;
    constexpr int LDC = 132;
    constexpr int V8 = TP2 * K / 8;
    constexpr int VPT = (V8 + 255) / 256;
    extern __shared__ char sgc[];
    __nv_bfloat16* ws = (__nv_bfloat16*)sgc;
    __nv_bfloat16* as = ws + K * LDW;
    float* cs = (float*)sgc;
    __shared__ float bs[128];
    __shared__ float red[8][4];

    const int tid = threadIdx.x;
    const int bid = blockIdx.x;

    if (tid < 128) bs[tid] = bias[tid];
    for (int i = tid; i < K * 32; i += 256) {
        int k = i >> 5, c4 = i & 31;
        float4 v = *(const float4*)&W[k * 128 + c4 * 4];
        __nv_bfloat16* p = &ws[k * LDW + c4 * 4];
        p[0] = __float2bfloat16(v.x); p[1] = __float2bfloat16(v.y);
        p[2] = __float2bfloat16(v.z); p[3] = __float2bfloat16(v.w);
    }
    for (int i = tid; i < 6 * (K / 8); i += 256) {
        int r = 122 + i / (K / 8), c8 = i % (K / 8);
        *(uint4*)&as[r * LDA + c8 * 8] = make_uint4(0, 0, 0, 0);
    }

#pragma unroll 1
    for (int nh = 0; nh < 2; nh++) {
        const int n = 2 * bid + nh;
        const uint4* hn = (const uint4*)(h + (size_t)n * (TP2 * K));
        u64b accp[VPT][4];
#pragma unroll
        for (int v = 0; v < VPT; v++) {
            int i = tid + v * 256;
            if (i < V8) {
                uint4 b = hn[i];
                accp[v][0] = expand_bf2(b.x);
                accp[v][1] = expand_bf2(b.y);
                accp[v][2] = expand_bf2(b.z);
                accp[v][3] = expand_bf2(b.w);
            }
        }
        const int jb = g_off[n], je = g_off[n + 1];
        int e = jb;
        if (VPT == 1) {
            for (; e + 4 <= je; e += 4) {
                const uint4* p0 = (const uint4*)(h + (size_t)g_col[e]     * (TP2 * K));
                const uint4* p1 = (const uint4*)(h + (size_t)g_col[e + 1] * (TP2 * K));
                const uint4* p2 = (const uint4*)(h + (size_t)g_col[e + 2] * (TP2 * K));
                const uint4* p3 = (const uint4*)(h + (size_t)g_col[e + 3] * (TP2 * K));
                if (tid < V8) {
                    uint4 b0 = p0[tid], b1 = p1[tid], b2 = p2[tid], b3 = p3[tid];
                    acc_pair_u4(accp[0], b0, b1);
                    acc_pair_u4(accp[0], b2, b3);
                }
            }
        } else {
            for (; e + 3 <= je; e += 3) {
                const uint4* p0 = (const uint4*)(h + (size_t)g_col[e]     * (TP2 * K));
                const uint4* p1 = (const uint4*)(h + (size_t)g_col[e + 1] * (TP2 * K));
                const uint4* p2 = (const uint4*)(h + (size_t)g_col[e + 2] * (TP2 * K));
                uint4 b0[VPT], b1[VPT], b2[VPT];
#pragma unroll
                for (int v = 0; v < VPT; v++) {
                    int i = tid + v * 256;
                    if (i < V8) { b0[v] = p0[i]; b1[v] = p1[i]; b2[v] = p2[i]; }
                }
#pragma unroll
                for (int v = 0; v < VPT; v++) {
                    int i = tid + v * 256;
                    if (i < V8) { acc_pair_u4(accp[v], b0[v], b1[v]); acc_u4(accp[v], b2[v]); }
                }
            }
        }
        for (; e + 2 <= je; e += 2) {
            const uint4* p0 = (const uint4*)(h + (size_t)g_col[e]     * (TP2 * K));
            const uint4* p1 = (const uint4*)(h + (size_t)g_col[e + 1] * (TP2 * K));
            uint4 b0[VPT], b1[VPT];
#pragma unroll
            for (int v = 0; v < VPT; v++) {
                int i = tid + v * 256;
                if (i < V8) { b0[v] = p0[i]; b1[v] = p1[i]; }
            }
#pragma unroll
            for (int v = 0; v < VPT; v++) {
                int i = tid + v * 256;
                if (i < V8) acc_pair_u4(accp[v], b0[v], b1[v]);
            }
        }
        if (e < je) {
            const uint4* p0 = (const uint4*)(h + (size_t)g_col[e] * (TP2 * K));
#pragma unroll
            for (int v = 0; v < VPT; v++) {
                int i = tid + v * 256;
                if (i < V8) acc_u4(accp[v], p0[i]);
            }
        }
#pragma unroll
        for (int v = 0; v < VPT; v++) {
            int i = tid + v * 256;
            if (i < V8) {
                int r = nh * TP2 + i / (K / 8), c8 = i % (K / 8);
                uint4 o;
                o.x = pair_to_bf2(accp[v][0]);
                o.y = pair_to_bf2(accp[v][1]);
                o.z = pair_to_bf2(accp[v][2]);
                o.w = pair_to_bf2(accp[v][3]);
                *(uint4*)&as[r * LDA + c8 * 8] = o;
            }
        }
    }
    __syncthreads();

    const int wid = tid >> 5;
    const int wr = wid & 3;
    const int wc = wid >> 2;
    wmma::fragment<wmma::accumulator, 16, 16, 16, float> cf[2][4];
#pragma unroll
    for (int i = 0; i < 2; i++)
#pragma unroll
        for (int j = 0; j < 4; j++) wmma::fill_fragment(cf[i][j], 0.f);

#pragma unroll
    for (int k0 = 0; k0 < K; k0 += 16) {
        wmma::fragment<wmma::matrix_a, 16, 16, 16, __nv_bfloat16, wmma::row_major> af[2];
#pragma unroll
        for (int i = 0; i < 2; i++)
            wmma::load_matrix_sync(af[i], as + (wr * 32 + i * 16) * LDA + k0, LDA);
        wmma::fragment<wmma::matrix_b, 16, 16, 16, __nv_bfloat16, wmma::row_major> bf[4];
#pragma unroll
        for (int j = 0; j < 4; j++)
            wmma::load_matrix_sync(bf[j], ws + k0 * LDW + wc * 64 + j * 16, LDW);
#pragma unroll
        for (int i = 0; i < 2; i++)
#pragma unroll
            for (int j = 0; j < 4; j++)
                wmma::mma_sync(cf[i][j], af[i], bf[j], cf[i][j]);
    }
    __syncthreads();
#pragma unroll
    for (int i = 0; i < 2; i++)
#pragma unroll
        for (int j = 0; j < 4; j++)
            wmma::store_matrix_sync(cs + (wr * 32 + i * 16) * LDC + wc * 64 + j * 16,
                                    cf[i][j], LDC, wmma::mem_row_major);
    __syncthreads();

    if (!DO_CONTRIB) {
        for (int idx = tid; idx < 128 * 64; idx += 256) {
            int r = idx >> 6, c2 = idx & 63;
            if (r < 122) {
                int nh = (r >= TP2) ? 1 : 0;
                int n = 2 * bid + nh;
                int t = r - TP2 * nh;
                float dv = g_dinv[n];
                float v0 = fmaxf(cs[r * LDC + 2 * c2]     * dv + bs[2 * c2], 0.f) * dv;
                float v1 = fmaxf(cs[r * LDC + 2 * c2 + 1] * dv + bs[2 * c2 + 1], 0.f) * dv;
                ((__nv_bfloat162*)out)[(size_t)(n * TP2 + t) * 64 + c2] =
                    __floats2bfloat162_rn(v0, v1);
            }
        }
    } else {
        const int half = tid >> 7, d = tid & 127;
        const int n = 2 * bid + half;
        const float dv = g_dinv[n];
        const float bsv = bs[d];
        float a0 = 0.f, a1 = 0.f, a2 = 0.f, a3 = 0.f;
#pragma unroll 4
        for (int t = 0; t < TP2; t++) {
            float v = fmaxf(cs[(half * TP2 + t) * LDC + d] * dv + bsv, 0.f);
            const float4 w = *(const float4*)&g_dwt[(size_t)(t * DD + d) * 4];
            a0 += v * w.x; a1 += v * w.y; a2 += v * w.z; a3 += v * w.w;
        }
#pragma unroll
        for (int o = 16; o > 0; o >>= 1) {
            a0 += __shfl_down_sync(0xffffffff, a0, o);
            a1 += __shfl_down_sync(0xffffffff, a1, o);
            a2 += __shfl_down_sync(0xffffffff, a2, o);
            a3 += __shfl_down_sync(0xffffffff, a3, o);
        }
        const int wid2 = tid >> 5;
        if ((tid & 31) == 0) {
            red[wid2][0] = a0; red[wid2][1] = a1; red[wid2][2] = a2; red[wid2][3] = a3;
        }
        __syncthreads();
        if (tid < 8) {
            int hh = tid >> 2, j = tid & 3;
            float s = red[hh * 4 + 0][j] + red[hh * 4 + 1][j]
                    + red[hh * 4 + 2][j] + red[hh * 4 + 3][j];
            g_contrib[(2 * bid + hh) * 4 + j] = s;
        }
    }
}

// ---------------- batch pooling + bias + log_softmax ----------------
__global__ __launch_bounds__(256) void final_kernel(
    const int* __restrict__ batch, const float* __restrict__ db,
    float* __restrict__ out)
{
    const int b = blockIdx.x, tid = threadIdx.x;
    float a0 = 0.f, a1 = 0.f, a2 = 0.f, a3 = 0.f;
    int c = 0;
    for (int n = tid; n < NN; n += 256) {
        if (batch[n] == b) {
            const float4 v = *(const float4*)&g_contrib[n * 4];
            a0 += v.x; a1 += v.y; a2 += v.z; a3 += v.w;
            c++;
        }
    }
    __shared__ float r0[256], r1[256], r2[256], r3[256];
    __shared__ int rc[256];
    r0[tid] = a0; r1[tid] = a1; r2[tid] = a2; r3[tid] = a3; rc[tid] = c;
    __syncthreads();
    for (int s = 128; s > 0; s >>= 1) {
        if (tid < s) {
            r0[tid] += r0[tid + s]; r1[tid] += r1[tid + s];
            r2[tid] += r2[tid + s]; r3[tid] += r3[tid + s];
            rc[tid] += rc[tid + s];
        }
        __syncthreads();
    }
    if (tid == 0) {
        float cc = fmaxf((float)rc[0], 1.f);
        float l0 = r0[0] / cc + db[0];
        float l1 = r1[0] / cc + db[1];
        float l2 = r2[0] / cc + db[2];
        float l3 = r3[0] / cc + db[3];
        float m = fmaxf(fmaxf(l0, l1), fmaxf(l2, l3));
        float sum = expf(l0 - m) + expf(l1 - m) + expf(l2 - m) + expf(l3 - m);
        float ls = logf(sum);
        out[b * 4 + 0] = l0 - m - ls;
        out[b * 4 + 1] = l1 - m - ls;
        out[b * 4 + 2] = l2 - m - ls;
        out[b * 4 + 3] = l3 - m - ls;
    }
}

// ---------------- launch ----------------
extern "C" void kernel_launch(void* const* d_in, const int* in_sizes, int n_in,
                              void* d_out, int out_size)
{
    const float* x   = (const float*)d_in[0];
    const float* pos = (const float*)d_in[1];
    const float* c1w = (const float*)d_in[2];
    const float* c1b = (const float*)d_in[3];
    const float* bg1 = (const float*)d_in[4];
    const float* bb1 = (const float*)d_in[5];
    const float* c2w = (const float*)d_in[6];
    const float* c2b = (const float*)d_in[7];
    const float* bg2 = (const float*)d_in[8];
    const float* bb2 = (const float*)d_in[9];
    const float* c3w = (const float*)d_in[10];
    const float* c3b = (const float*)d_in[11];
    const float* bg3 = (const float*)d_in[12];
    const float* bb3 = (const float*)d_in[13];
    const float* pw1 = (const float*)d_in[14];
    const float* pb1 = (const float*)d_in[15];
    const float* pw2 = (const float*)d_in[16];
    const float* pb2 = (const float*)d_in[17];
    const float* gw1 = (const float*)d_in[18];
    const float* gb1 = (const float*)d_in[19];
    const float* gw2 = (const float*)d_in[20];
    const float* gb2 = (const float*)d_in[21];
    const float* dw  = (const float*)d_in[22];
    const float* db  = (const float*)d_in[23];
    const int*   ei  = (const int*)d_in[24];
    const int*   bat = (const int*)d_in[25];
    float* out = (float*)d_out;

    const int g1_smem = 128 * 132 * 4;                    // 67584
    const int g2_smem = (128 * 136 + 128 * 136) * 2;      // 69632

    cudaFuncSetAttribute(conv_kernel, cudaFuncAttributeMaxDynamicSharedMemorySize, CONV_SMEM_BYTES);
    cudaFuncSetAttribute(gcn_fused_kernel<32, false>,  cudaFuncAttributeMaxDynamicSharedMemorySize, g1_smem);
    cudaFuncSetAttribute(gcn_fused_kernel<128, true>,  cudaFuncAttributeMaxDynamicSharedMemorySize, g2_smem);

    __nv_bfloat16 *h0, *h1;
    cudaGetSymbolAddress((void**)&h0, g_h0);
    cudaGetSymbolAddress((void**)&h1, g_h1);

    // conv stays 4th launch (profiled)
    zero_dwt_kernel<<<8, 256>>>(dw);
    count_kernel<<<64, 256>>>(ei);
    scan_kernel<<<1, 256>>>();

    conv_kernel<<<NN, 256, CONV_SMEM_BYTES>>>(
        x, pos, c1w, c1b, bg1, bb1, c2w, c2b, bg2, bb2,
        c3w, c3b, bg3, bb3, pw1, pb1, pw2, pb2, h0);

    fill_kernel<<<64, 256>>>(ei);

    gcn_fused_kernel<32, false><<<NN / 2, 256, g1_smem>>>(h0, gw1, gb1, h1);
    gcn_fused_kernel<128, true><<<NN / 2, 256, g2_smem>>>(h1, gw2, gb2, nullptr);

    final_kernel<<<BBATCH, 256>>>(bat, db, out);
}

// round 17
// speedup vs baseline: 1.0856x; 1.0702x over previous
#include <cuda_runtime.h>
#include <cuda_bf16.h>
#include <math.h>
#include <mma.h>

using namespace nvcuda;

#define NN     2048
#define EE     16384
#define BBATCH 32
#define TP2    61
#define DD     128
#define C3N    32

typedef unsigned long long u64b;

__device__ __forceinline__ void fma2(u64b& d, u64b a, u64b b) {
    asm("fma.rn.f32x2 %0, %1, %2, %0;" : "+l"(d) : "l"(a), "l"(b));
}
__device__ __forceinline__ float hsum2(u64b v) {
    float lo, hi;
    asm("mov.b64 {%0,%1}, %2;" : "=f"(lo), "=f"(hi) : "l"(v));
    return lo + hi;
}
__device__ __forceinline__ u64b expand_bf2(unsigned u) {
    unsigned lo = u << 16;
    unsigned hi = u & 0xffff0000u;
    u64b d;
    asm("mov.b64 %0, {%1, %2};" : "=l"(d) : "r"(lo), "r"(hi));
    return d;
}
__device__ __forceinline__ void add2(u64b& d, u64b a) {
    asm("add.rn.f32x2 %0, %0, %1;" : "+l"(d) : "l"(a));
}
__device__ __forceinline__ unsigned bfadd2(unsigned a, unsigned b) {
    unsigned r;
    asm("add.rn.bf16x2 %0, %1, %2;" : "=r"(r) : "r"(a), "r"(b));
    return r;
}
__device__ __forceinline__ void acc_u4(u64b* accp, uint4 b) {
    add2(accp[0], expand_bf2(b.x));
    add2(accp[1], expand_bf2(b.y));
    add2(accp[2], expand_bf2(b.z));
    add2(accp[3], expand_bf2(b.w));
}
__device__ __forceinline__ void acc_pair_u4(u64b* accp, uint4 a, uint4 b) {
    add2(accp[0], expand_bf2(bfadd2(a.x, b.x)));
    add2(accp[1], expand_bf2(bfadd2(a.y, b.y)));
    add2(accp[2], expand_bf2(bfadd2(a.z, b.z)));
    add2(accp[3], expand_bf2(bfadd2(a.w, b.w)));
}
__device__ __forceinline__ unsigned pair_to_bf2(u64b d) {
    float lo, hi; unsigned r;
    asm("mov.b64 {%0,%1}, %2;" : "=f"(lo), "=f"(hi) : "l"(d));
    asm("cvt.rn.bf16x2.f32 %0, %1, %2;" : "=r"(r) : "f"(hi), "f"(lo));
    return r;
}
__device__ __forceinline__ unsigned bf2pack(float lo, float hi) {
    unsigned r;
    asm("cvt.rn.bf16x2.f32 %0, %1, %2;" : "=r"(r) : "f"(hi), "f"(lo));
    return r;
}

// ---------------- scratch ----------------
__device__ __nv_bfloat16 g_h0[NN * TP2 * C3N];
__device__ __nv_bfloat16 g_h1[NN * TP2 * DD];
__device__ float g_dwt[TP2 * DD * 4];
__device__ float g_contrib[NN * 4];
__device__ float g_dinv[NN];
__device__ int   g_cnt[NN];
__device__ int   g_cur[NN];
__device__ int   g_off[NN + 1];
__device__ int   g_col[EE];

// ---------------- graph prep ----------------
__global__ void zero_dwt_kernel(const float* __restrict__ dw) {
    int i = blockIdx.x * blockDim.x + threadIdx.x;
    if (i < NN) g_cnt[i] = 0;
    for (int j = i; j < TP2 * DD; j += 2048) {
        int t = j >> 7, d = j & 127;
        *(float4*)&g_dwt[j * 4] = *(const float4*)&dw[(size_t)(d * TP2 + t) * 4];
    }
}

__global__ void count_kernel(const int* __restrict__ ei) {
    int e = blockIdx.x * blockDim.x + threadIdx.x;
    if (e < EE) atomicAdd(&g_cnt[ei[EE + e]], 1);
}

__global__ void scan_kernel() {
    __shared__ int csum[256];
    const int tid = threadIdx.x;
    const int base = tid * 8;
    int local[8];
    int s = 0;
#pragma unroll
    for (int i = 0; i < 8; i++) { local[i] = s; s += g_cnt[base + i]; }
    csum[tid] = s;
    __syncthreads();
    for (int ofs = 1; ofs < 256; ofs <<= 1) {
        int v = (tid >= ofs) ? csum[tid - ofs] : 0;
        __syncthreads();
        csum[tid] += v;
        __syncthreads();
    }
    int pre = (tid == 0) ? 0 : csum[tid - 1];
#pragma unroll
    for (int i = 0; i < 8; i++) {
        int o = pre + local[i];
        g_off[base + i] = o;
        g_cur[base + i] = o;
        g_dinv[base + i] = rsqrtf((float)(g_cnt[base + i] + 1));
    }
    if (tid == 255) g_off[NN] = pre + s;
}

__global__ void fill_kernel(const int* __restrict__ ei) {
    int e = blockIdx.x * blockDim.x + threadIdx.x;
    if (e < EE) {
        int src = ei[e];
        int dst = ei[EE + e];
        int p = atomicAdd(&g_cur[dst], 1);
        g_col[p] = src;
    }
}

// ---------------- fused CNN + pos-MLP: conv1 f32x2, conv2 WMMA bf16, conv3 f32x2 ----------------
// smem float-slot layout:
//  region X [0,6144): phase1 sxp@0(1048) h1b@1048(4112) | phase2 As@0(1024) h2raw@1024(4160, col-major ld260)
//  region Y [6144,14400): u1b bf16@6144 (8ch x 520 u32 = 4160 u32) | phase3 u2@6144(3968) w3k@10304(4096)
//  persistent [14408,16008): w1e/w1o/w1x, Btile bf16, s/B/pe/hid
#define SXP_O   0
#define H1B_O   1048
#define A_O     0
#define H2R_O   1024
#define U1U_O   6144      // unsigned index (bf16x2 words), 8 channels x 520
#define U2_O    6144
#define W3K_O   10304
#define W1E_O   14408
#define W1O_O   14600
#define W1X_O   14792
#define BT_O    14808
#define S1_O    15832
#define B1_O    15840
#define S2_O    15848
#define B2_O    15864
#define S3_O    15880
#define B3_O    15912
#define PE_O    15944
#define HID_O   15976
#define CONV_SMEM_FLOATS 16008
#define CONV_SMEM_BYTES (CONV_SMEM_FLOATS * 4)

__global__ __launch_bounds__(256, 3) void conv_kernel(
    const float* __restrict__ x,   const float* __restrict__ pos,
    const float* __restrict__ c1w, const float* __restrict__ c1b,
    const float* __restrict__ g1,  const float* __restrict__ b1,
    const float* __restrict__ c2w, const float* __restrict__ c2b,
    const float* __restrict__ g2,  const float* __restrict__ b2,
    const float* __restrict__ c3w, const float* __restrict__ c3b,
    const float* __restrict__ g3,  const float* __restrict__ b3,
    const float* __restrict__ pw1, const float* __restrict__ pb1,
    const float* __restrict__ pw2, const float* __restrict__ pb2,
    __nv_bfloat16* __restrict__ out)
{
    extern __shared__ float sm[];
    unsigned* smu = (unsigned*)sm;
    const int n = blockIdx.x;
    const int tid = threadIdx.x;
    const float rs = rsqrtf(1.0f + 1e-5f);
    const float dvn = g_dinv[n];

    // conv1 weights (paired)
    for (int i = tid; i < 96; i += 256) {
        int c = i / 12, m = i % 12;
        sm[W1E_O + 2 * i]     = c1w[c * 25 + 2 * m];
        sm[W1E_O + 2 * i + 1] = c1w[c * 25 + 2 * m + 1];
    }
    for (int i = tid; i < 96; i += 256) {
        int c = i / 12, m = i % 12;
        sm[W1O_O + 2 * i]     = c1w[c * 25 + 2 * m + 1];
        sm[W1O_O + 2 * i + 1] = c1w[c * 25 + 2 * m + 2];
    }
    if (tid < 8)  sm[W1X_O + tid] = c1w[tid * 25];
    else if (tid < 16) sm[W1X_O + tid] = c1w[(tid - 8) * 25 + 24];
    // conv2 B tile: Bt[ci][k][c] bf16, k=15 row zero
    {
        __nv_bfloat16* Bt = (__nv_bfloat16*)&sm[BT_O];
        for (int i = tid; i < 2048; i += 256) {
            int ci = i >> 8, k = (i >> 4) & 15, c = i & 15;
            float v = (k < 15) ? c2w[c * 120 + ci * 15 + k] : 0.f;
            Bt[i] = __float2bfloat16(v);
        }
    }
    if (tid < 8) {
        float s = g1[tid] * rs; sm[S1_O + tid] = s; sm[B1_O + tid] = c1b[tid] * s + b1[tid];
    } else if (tid >= 32 && tid < 48) {
        int c = tid - 32; float s = g2[c] * rs; sm[S2_O + c] = s; sm[B2_O + c] = c2b[c] * s + b2[c];
    } else if (tid >= 64 && tid < 96) {
        int c = tid - 64; float s = g3[c] * rs; sm[S3_O + c] = s; sm[B3_O + c] = c3b[c] * s + b3[c];
    }
    if (tid >= 128 && tid < 160) {
        int c = tid - 128;
        float p0 = pos[n * 3 + 0], p1 = pos[n * 3 + 1], p2 = pos[n * 3 + 2];
        float h = p0 * pw1[c] + p1 * pw1[32 + c] + p2 * pw1[64 + c] + pb1[c];
        sm[HID_O + c] = fmaxf(h, 0.f);
    }
    for (int i = tid; i < 1024; i += 256) sm[SXP_O + 12 + i] = x[(size_t)n * 1024 + i];
    if (tid < 12) { sm[SXP_O + tid] = 0.f; sm[SXP_O + 1036 + tid] = 0.f; }
    __syncthreads();

    if (tid < 32) {                       // pos-MLP layer 2
        float s = pb2[tid];
#pragma unroll
        for (int j = 0; j < 32; j++) s += sm[HID_O + j] * pw2[j * 32 + tid];
        sm[PE_O + tid] = s;
    }

    // conv1 (1->8, K=25) + BN + relu, write bf16 h1b
    {
        const int t0 = tid * 4;
        union UU { float4 q[7]; u64b p[14]; float f[28]; } uu;
#pragma unroll
        for (int i = 0; i < 7; i++) uu.q[i] = *(const float4*)&sm[SXP_O + t0 + 4 * i];
        const u64b* w1e = (const u64b*)&sm[W1E_O];
        const u64b* w1o = (const u64b*)&sm[W1O_O];
#pragma unroll
        for (int c = 0; c < 8; c++) {
            u64b a0 = 0, a1 = 0, a2 = 0, a3 = 0;
#pragma unroll
            for (int m = 0; m < 12; m++) {
                u64b we = w1e[c * 12 + m];
                fma2(a0, we, uu.p[m]);
                fma2(a2, we, uu.p[m + 1]);
                u64b wo = w1o[c * 12 + m];
                fma2(a1, wo, uu.p[m + 1]);
                fma2(a3, wo, uu.p[m + 2]);
            }
            float w0 = sm[W1X_O + c], w24 = sm[W1X_O + 8 + c];
            float v0 = hsum2(a0) + w24 * uu.f[24];
            float v1 = hsum2(a1) + w0  * uu.f[1];
            float v2 = hsum2(a2) + w24 * uu.f[26];
            float v3 = hsum2(a3) + w0  * uu.f[3];
            float s = sm[S1_O + c], B = sm[B1_O + c];
            float o0 = fmaxf(v0 * s + B, 0.f);
            float o1 = fmaxf(v1 * s + B, 0.f);
            float o2 = fmaxf(v2 * s + B, 0.f);
            float o3 = fmaxf(v3 * s + B, 0.f);
            uint2 pk;
            pk.x = bf2pack(o0, o1);
            pk.y = bf2pack(o2, o3);
            *(uint2*)&smu[H1B_O + c * 514 + (t0 >> 1)] = pk;
        }
    }
    __syncthreads();

    // pool1: u1 bf16 (channel stride 520 u32-words) from bf16 h1b; zero guard
    {
        unsigned* u1u = &smu[U1U_O];
        for (int c = 0; c < 8; c++) {
            const unsigned* hb = &smu[H1B_O + c * 514];
            for (int j2 = tid; j2 < 510; j2 += 256) {
                unsigned a = hb[j2], b = hb[j2 + 1], d = hb[j2 + 2];
                float a0 = __uint_as_float(a << 16), a1 = __uint_as_float(a & 0xffff0000u);
                float b0 = __uint_as_float(b << 16), b1 = __uint_as_float(b & 0xffff0000u);
                float d0 = __uint_as_float(d << 16);
                float mid = a1 + b0 + b1;
                u1u[c * 520 + j2] = bf2pack(0.25f * (a0 + mid), 0.25f * (mid + d0));
            }
        }
        if (tid < 80) u1u[(tid / 10) * 520 + 510 + (tid % 10)] = 0;
    }
    __syncthreads();

    // ---- conv2 via WMMA: warp-local A staging (syncwarp only), fp32 accum -> h2raw col-major ----
    {
        __nv_bfloat16* As = (__nv_bfloat16*)&sm[A_O];
        const __nv_bfloat16* Bt = (const __nv_bfloat16*)&sm[BT_O];
        float* h2r = &sm[H2R_O];
        const unsigned* u1u = &smu[U1U_O];
        const int wid = tid >> 5;
        const int r = tid >> 1, half = tid & 1;
#pragma unroll 1
        for (int chunk = 0; chunk < 2; chunk++) {
            wmma::fragment<wmma::accumulator, 16, 16, 16, float> cf;
            wmma::fill_fragment(cf, 0.f);
#pragma unroll 1
            for (int ci = 0; ci < 8; ci++) {
                int off = ci * 520 + 2 * (chunk * 128 + r) + 4 * half;
                uint2 q0 = *(const uint2*)&u1u[off];
                uint2 q1 = *(const uint2*)&u1u[off + 2];
                __syncwarp();   // prior fragment load done (warp-local tile)
                *(uint4*)&As[r * 16 + 8 * half] = make_uint4(q0.x, q0.y, q1.x, q1.y);
                __syncwarp();   // A visible within warp
                wmma::fragment<wmma::matrix_a, 16, 16, 16, __nv_bfloat16, wmma::row_major> af;
                wmma::load_matrix_sync(af, As + wid * 256, 16);
                wmma::fragment<wmma::matrix_b, 16, 16, 16, __nv_bfloat16, wmma::row_major> bfr;
                wmma::load_matrix_sync(bfr, Bt + ci * 256, 16);
                wmma::mma_sync(cf, af, bfr, cf);
            }
            wmma::store_matrix_sync(h2r + chunk * 128 + wid * 16, cf, 260,
                                    wmma::mem_col_major);
        }
        __syncthreads();
    }

    // ---- pool2 (conflict-free col-major reads) + load conv3 weights ----
    for (int c = 0; c < 16; c++) {
        if (tid < 248) {
            float sc = sm[S2_O + c], bb = sm[B2_O + c];
            const float* hr = &sm[H2R_O + c * 260];
            float s = 0.f;
#pragma unroll
            for (int d = 0; d < 4; d++)
                s += fmaxf(hr[tid + d] * sc + bb, 0.f);
            sm[U2_O + c * 248 + tid] = 0.25f * s;
        }
    }
    for (int i = tid; i < 1024; i += 256) {
        int ci = i >> 6, m = (i >> 4) & 3, q = i & 15;
        int base = q * 112 + ci * 7 + 2 * m;
        float4 v;
        v.x = c3w[base];
        v.y = (2 * m + 1 < 7) ? c3w[base + 1] : 0.f;
        v.z = c3w[base + 1792];
        v.w = (2 * m + 1 < 7) ? c3w[base + 1793] : 0.f;
        *(float4*)&sm[W3K_O + 4 * i] = v;
    }
    __syncthreads();

    // conv3 (16->32, K=7 padded 8) fused pool4 + pe, write bf16 pre-scaled by dinv[n]
    {
        const int q = tid & 15, tpq = tid >> 4;
        u64b accL[4], accH[4];
#pragma unroll
        for (int it = 0; it < 4; it++) { accL[it] = 0; accH[it] = 0; }
#pragma unroll
        for (int ci = 0; ci < 16; ci++) {
            union WU { float4 v; u64b p[2]; } wv[4];
#pragma unroll
            for (int m = 0; m < 4; m++)
                wv[m].v = *(const float4*)&sm[W3K_O + 4 * ((ci * 4 + m) * 16 + q)];
#pragma unroll
            for (int it = 0; it < 4; it++) {
                int tp = tpq + 16 * it;
                if (tp < 61) {
                    union UB { float4 v[2]; u64b p[4]; } ub;
                    const float4* up = (const float4*)&sm[U2_O + ci * 248 + 4 * tp];
                    ub.v[0] = up[0]; ub.v[1] = up[1];
#pragma unroll
                    for (int m = 0; m < 4; m++) {
                        fma2(accL[it], wv[m].p[0], ub.p[m]);
                        fma2(accH[it], wv[m].p[1], ub.p[m]);
                    }
                }
            }
        }
        float sL = sm[S3_O + q], BL = sm[B3_O + q], peL = sm[PE_O + q];
        float sH = sm[S3_O + q + 16], BH = sm[B3_O + q + 16], peH = sm[PE_O + q + 16];
#pragma unroll
        for (int it = 0; it < 4; it++) {
            int tp = tpq + 16 * it;
            if (tp < 61) {
                size_t base = ((size_t)n * 61 + tp) * 32;
                out[base + q]      = __float2bfloat16((fmaxf(hsum2(accL[it]) * sL + BL, 0.f) + peL) * dvn);
                out[base + q + 16] = __float2bfloat16((fmaxf(hsum2(accH[it]) * sH + BH, 0.f) + peH) * dvn);
            }
        }
    }
}

// ---------------- fused GCN layer (2 nodes/block, M=128 tile) ----------------
template <int K, bool DO_CONTRIB>
__global__ __launch_bounds__(256, 2) void gcn_fused_kernel(
    const __nv_bfloat16* __restrict__ h, const float* __restrict__ W,
    const float* __restrict__ bias, __nv_bfloat16* __restrict__ out)
{
    constexpr int LDA = K + 8;
    constexpr int LDW = 136;
    constexpr int LDC = 132;
    constexpr int V8 = TP2 * K / 8;
    constexpr int VPT = (V8 + 255) / 256;
    extern __shared__ char sgc[];
    __nv_bfloat16* ws = (__nv_bfloat16*)sgc;
    __nv_bfloat16* as = ws + K * LDW;
    float* cs = (float*)sgc;
    __shared__ float bs[128];
    __shared__ float red[8][4];

    const int tid = threadIdx.x;
    const int bid = blockIdx.x;

    if (tid < 128) bs[tid] = bias[tid];
    for (int i = tid; i < K * 32; i += 256) {
        int k = i >> 5, c4 = i & 31;
        float4 v = *(const float4*)&W[k * 128 + c4 * 4];
        __nv_bfloat16* p = &ws[k * LDW + c4 * 4];
        p[0] = __float2bfloat16(v.x); p[1] = __float2bfloat16(v.y);
        p[2] = __float2bfloat16(v.z); p[3] = __float2bfloat16(v.w);
    }
    for (int i = tid; i < 6 * (K / 8); i += 256) {
        int r = 122 + i / (K / 8), c8 = i % (K / 8);
        *(uint4*)&as[r * LDA + c8 * 8] = make_uint4(0, 0, 0, 0);
    }

#pragma unroll 1
    for (int nh = 0; nh < 2; nh++) {
        const int n = 2 * bid + nh;
        const uint4* hn = (const uint4*)(h + (size_t)n * (TP2 * K));
        u64b accp[VPT][4];
#pragma unroll
        for (int v = 0; v < VPT; v++) {
            int i = tid + v * 256;
            if (i < V8) {
                uint4 b = hn[i];
                accp[v][0] = expand_bf2(b.x);
                accp[v][1] = expand_bf2(b.y);
                accp[v][2] = expand_bf2(b.z);
                accp[v][3] = expand_bf2(b.w);
            }
        }
        const int jb = g_off[n], je = g_off[n + 1];
        int e = jb;
        if (VPT == 1) {
            for (; e + 4 <= je; e += 4) {
                const uint4* p0 = (const uint4*)(h + (size_t)g_col[e]     * (TP2 * K));
                const uint4* p1 = (const uint4*)(h + (size_t)g_col[e + 1] * (TP2 * K));
                const uint4* p2 = (const uint4*)(h + (size_t)g_col[e + 2] * (TP2 * K));
                const uint4* p3 = (const uint4*)(h + (size_t)g_col[e + 3] * (TP2 * K));
                if (tid < V8) {
                    uint4 b0 = p0[tid], b1 = p1[tid], b2 = p2[tid], b3 = p3[tid];
                    acc_pair_u4(accp[0], b0, b1);
                    acc_pair_u4(accp[0], b2, b3);
                }
            }
        } else {
            for (; e + 3 <= je; e += 3) {
                const uint4* p0 = (const uint4*)(h + (size_t)g_col[e]     * (TP2 * K));
                const uint4* p1 = (const uint4*)(h + (size_t)g_col[e + 1] * (TP2 * K));
                const uint4* p2 = (const uint4*)(h + (size_t)g_col[e + 2] * (TP2 * K));
                uint4 b0[VPT], b1[VPT], b2[VPT];
#pragma unroll
                for (int v = 0; v < VPT; v++) {
                    int i = tid + v * 256;
                    if (i < V8) { b0[v] = p0[i]; b1[v] = p1[i]; b2[v] = p2[i]; }
                }
#pragma unroll
                for (int v = 0; v < VPT; v++) {
                    int i = tid + v * 256;
                    if (i < V8) { acc_pair_u4(accp[v], b0[v], b1[v]); acc_u4(accp[v], b2[v]); }
                }
            }
        }
        for (; e + 2 <= je; e += 2) {
            const uint4* p0 = (const uint4*)(h + (size_t)g_col[e]     * (TP2 * K));
            const uint4* p1 = (const uint4*)(h + (size_t)g_col[e + 1] * (TP2 * K));
            uint4 b0[VPT], b1[VPT];
#pragma unroll
            for (int v = 0; v < VPT; v++) {
                int i = tid + v * 256;
                if (i < V8) { b0[v] = p0[i]; b1[v] = p1[i]; }
            }
#pragma unroll
            for (int v = 0; v < VPT; v++) {
                int i = tid + v * 256;
                if (i < V8) acc_pair_u4(accp[v], b0[v], b1[v]);
            }
        }
        if (e < je) {
            const uint4* p0 = (const uint4*)(h + (size_t)g_col[e] * (TP2 * K));
#pragma unroll
            for (int v = 0; v < VPT; v++) {
                int i = tid + v * 256;
                if (i < V8) acc_u4(accp[v], p0[i]);
            }
        }
#pragma unroll
        for (int v = 0; v < VPT; v++) {
            int i = tid + v * 256;
            if (i < V8) {
                int r = nh * TP2 + i / (K / 8), c8 = i % (K / 8);
                uint4 o;
                o.x = pair_to_bf2(accp[v][0]);
                o.y = pair_to_bf2(accp[v][1]);
                o.z = pair_to_bf2(accp[v][2]);
                o.w = pair_to_bf2(accp[v][3]);
                *(uint4*)&as[r * LDA + c8 * 8] = o;
            }
        }
    }
    __syncthreads();

    const int wid = tid >> 5;
    const int wr = wid & 3;
    const int wc = wid >> 2;
    wmma::fragment<wmma::accumulator, 16, 16, 16, float> cf[2][4];
#pragma unroll
    for (int i = 0; i < 2; i++)
#pragma unroll
        for (int j = 0; j < 4; j++) wmma::fill_fragment(cf[i][j], 0.f);

#pragma unroll
    for (int k0 = 0; k0 < K; k0 += 16) {
        wmma::fragment<wmma::matrix_a, 16, 16, 16, __nv_bfloat16, wmma::row_major> af[2];
#pragma unroll
        for (int i = 0; i < 2; i++)
            wmma::load_matrix_sync(af[i], as + (wr * 32 + i * 16) * LDA + k0, LDA);
        wmma::fragment<wmma::matrix_b, 16, 16, 16, __nv_bfloat16, wmma::row_major> bf[4];
#pragma unroll
        for (int j = 0; j < 4; j++)
            wmma::load_matrix_sync(bf[j], ws + k0 * LDW + wc * 64 + j * 16, LDW);
#pragma unroll
        for (int i = 0; i < 2; i++)
#pragma unroll
            for (int j = 0; j < 4; j++)
                wmma::mma_sync(cf[i][j], af[i], bf[j], cf[i][j]);
    }
    __syncthreads();
#pragma unroll
    for (int i = 0; i < 2; i++)
#pragma unroll
        for (int j = 0; j < 4; j++)
            wmma::store_matrix_sync(cs + (wr * 32 + i * 16) * LDC + wc * 64 + j * 16,
                                    cf[i][j], LDC, wmma::mem_row_major);
    __syncthreads();

    if (!DO_CONTRIB) {
        for (int idx = tid; idx < 128 * 64; idx += 256) {
            int r = idx >> 6, c2 = idx & 63;
            if (r < 122) {
                int nh = (r >= TP2) ? 1 : 0;
                int n = 2 * bid + nh;
                int t = r - TP2 * nh;
                float dv = g_dinv[n];
                float v0 = fmaxf(cs[r * LDC + 2 * c2]     * dv + bs[2 * c2], 0.f) * dv;
                float v1 = fmaxf(cs[r * LDC + 2 * c2 + 1] * dv + bs[2 * c2 + 1], 0.f) * dv;
                ((__nv_bfloat162*)out)[(size_t)(n * TP2 + t) * 64 + c2] =
                    __floats2bfloat162_rn(v0, v1);
            }
        }
    } else {
        const int half = tid >> 7, d = tid & 127;
        const int n = 2 * bid + half;
        const float dv = g_dinv[n];
        const float bsv = bs[d];
        float a0 = 0.f, a1 = 0.f, a2 = 0.f, a3 = 0.f;
#pragma unroll 4
        for (int t = 0; t < TP2; t++) {
            float v = fmaxf(cs[(half * TP2 + t) * LDC + d] * dv + bsv, 0.f);
            const float4 w = *(const float4*)&g_dwt[(size_t)(t * DD + d) * 4];
            a0 += v * w.x; a1 += v * w.y; a2 += v * w.z; a3 += v * w.w;
        }
#pragma unroll
        for (int o = 16; o > 0; o >>= 1) {
            a0 += __shfl_down_sync(0xffffffff, a0, o);
            a1 += __shfl_down_sync(0xffffffff, a1, o);
            a2 += __shfl_down_sync(0xffffffff, a2, o);
            a3 += __shfl_down_sync(0xffffffff, a3, o);
        }
        const int wid2 = tid >> 5;
        if ((tid & 31) == 0) {
            red[wid2][0] = a0; red[wid2][1] = a1; red[wid2][2] = a2; red[wid2][3] = a3;
        }
        __syncthreads();
        if (tid < 8) {
            int hh = tid >> 2, j = tid & 3;
            float s = red[hh * 4 + 0][j] + red[hh * 4 + 1][j]
                    + red[hh * 4 + 2][j] + red[hh * 4 + 3][j];
            g_contrib[(2 * bid + hh) * 4 + j] = s;
        }
    }
}

// ---------------- batch pooling + bias + log_softmax ----------------
__global__ __launch_bounds__(256) void final_kernel(
    const int* __restrict__ batch, const float* __restrict__ db,
    float* __restrict__ out)
{
    const int b = blockIdx.x, tid = threadIdx.x;
    float a0 = 0.f, a1 = 0.f, a2 = 0.f, a3 = 0.f;
    int c = 0;
    for (int n = tid; n < NN; n += 256) {
        if (batch[n] == b) {
            const float4 v = *(const float4*)&g_contrib[n * 4];
            a0 += v.x; a1 += v.y; a2 += v.z; a3 += v.w;
            c++;
        }
    }
    __shared__ float r0[256], r1[256], r2[256], r3[256];
    __shared__ int rc[256];
    r0[tid] = a0; r1[tid] = a1; r2[tid] = a2; r3[tid] = a3; rc[tid] = c;
    __syncthreads();
    for (int s = 128; s > 0; s >>= 1) {
        if (tid < s) {
            r0[tid] += r0[tid + s]; r1[tid] += r1[tid + s];
            r2[tid] += r2[tid + s]; r3[tid] += r3[tid + s];
            rc[tid] += rc[tid + s];
        }
        __syncthreads();
    }
    if (tid == 0) {
        float cc = fmaxf((float)rc[0], 1.f);
        float l0 = r0[0] / cc + db[0];
        float l1 = r1[0] / cc + db[1];
        float l2 = r2[0] / cc + db[2];
        float l3 = r3[0] / cc + db[3];
        float m = fmaxf(fmaxf(l0, l1), fmaxf(l2, l3));
        float sum = expf(l0 - m) + expf(l1 - m) + expf(l2 - m) + expf(l3 - m);
        float ls = logf(sum);
        out[b * 4 + 0] = l0 - m - ls;
        out[b * 4 + 1] = l1 - m - ls;
        out[b * 4 + 2] = l2 - m - ls;
        out[b * 4 + 3] = l3 - m - ls;
    }
}

// ---------------- launch ----------------
extern "C" void kernel_launch(void* const* d_in, const int* in_sizes, int n_in,
                              void* d_out, int out_size)
{
    const float* x   = (const float*)d_in[0];
    const float* pos = (const float*)d_in[1];
    const float* c1w = (const float*)d_in[2];
    const float* c1b = (const float*)d_in[3];
    const float* bg1 = (const float*)d_in[4];
    const float* bb1 = (const float*)d_in[5];
    const float* c2w = (const float*)d_in[6];
    const float* c2b = (const float*)d_in[7];
    const float* bg2 = (const float*)d_in[8];
    const float* bb2 = (const float*)d_in[9];
    const float* c3w = (const float*)d_in[10];
    const float* c3b = (const float*)d_in[11];
    const float* bg3 = (const float*)d_in[12];
    const float* bb3 = (const float*)d_in[13];
    const float* pw1 = (const float*)d_in[14];
    const float* pb1 = (const float*)d_in[15];
    const float* pw2 = (const float*)d_in[16];
    const float* pb2 = (const float*)d_in[17];
    const float* gw1 = (const float*)d_in[18];
    const float* gb1 = (const float*)d_in[19];
    const float* gw2 = (const float*)d_in[20];
    const float* gb2 = (const float*)d_in[21];
    const float* dw  = (const float*)d_in[22];
    const float* db  = (const float*)d_in[23];
    const int*   ei  = (const int*)d_in[24];
    const int*   bat = (const int*)d_in[25];
    float* out = (float*)d_out;

    const int g1_smem = 128 * 132 * 4;                    // 67584
    const int g2_smem = (128 * 136 + 128 * 136) * 2;      // 69632

    cudaFuncSetAttribute(conv_kernel, cudaFuncAttributeMaxDynamicSharedMemorySize, CONV_SMEM_BYTES);
    cudaFuncSetAttribute(gcn_fused_kernel<32, false>,  cudaFuncAttributeMaxDynamicSharedMemorySize, g1_smem);
    cudaFuncSetAttribute(gcn_fused_kernel<128, true>,  cudaFuncAttributeMaxDynamicSharedMemorySize, g2_smem);

    __nv_bfloat16 *h0, *h1;
    cudaGetSymbolAddress((void**)&h0, g_h0);
    cudaGetSymbolAddress((void**)&h1, g_h1);

    // conv stays 4th launch (profiled)
    zero_dwt_kernel<<<8, 256>>>(dw);
    count_kernel<<<64, 256>>>(ei);
    scan_kernel<<<1, 256>>>();

    conv_kernel<<<NN, 256, CONV_SMEM_BYTES>>>(
        x, pos, c1w, c1b, bg1, bb1, c2w, c2b, bg2, bb2,
        c3w, c3b, bg3, bb3, pw1, pb1, pw2, pb2, h0);

    fill_kernel<<<64, 256>>>(ei);

    gcn_fused_kernel<32, false><<<NN / 2, 256, g1_smem>>>(h0, gw1, gb1, h1);
    gcn_fused_kernel<128, true><<<NN / 2, 256, g2_smem>>>(h1, gw2, gb2, nullptr);

    final_kernel<<<BBATCH, 256>>>(bat, db, out);
}